// round 15
// baseline (speedup 1.0000x reference)
#include <cuda_runtime.h>
#include <cuda_bf16.h>
#include <cuda_fp16.h>

#define K_NB    10
#define K_TOT   300
#define TPB     256
#define NWARP   (TPB / 32)
#define BLKS_PER_SM 6
#define NUM_SMS 148
#define KSTRIDE 40   // uint2 pair-slots per k-row (32 used + 8 pad)

// Control-point table: fused fp16, 16B/entry, one LDS.128 per gather:
//  sqb[j] = { h2(qw,qx), h2(qy,qz), h2(b0,b1), h2(b2,delta) }
// Per-warp staging slice: k-major transposed (w,idx) pairs, read at the
// 2-wavefront LDS.64 floor. Blend: sum = L*m + 2P + 2(G x m) + B.

__device__ __forceinline__ void quat_rotate(float cw, float cx, float cy, float cz,
                                            float vx, float vy, float vz,
                                            float& ox, float& oy, float& oz)
{
    float tx = cy * vz - cz * vy;
    float ty = cz * vx - cx * vz;
    float tz = cx * vy - cy * vx;
    float ux = cy * tz - cz * ty;
    float uy = cz * tx - cx * tz;
    float uz = cx * ty - cy * tx;
    ox = fmaf(2.f, fmaf(cw, tx, ux), vx);
    oy = fmaf(2.f, fmaf(cw, ty, uy), vy);
    oz = fmaf(2.f, fmaf(cw, tz, uz), vz);
}

__device__ __forceinline__ unsigned int pack_h2(float a, float b)
{
    __half2 h = __floats2half2_rn(a, b);
    return *reinterpret_cast<unsigned int*>(&h);
}

__global__ __launch_bounds__(TPB, BLKS_PER_SM)
void deform4d_kernel(const float* __restrict__ means,
                     const float* __restrict__ quats,
                     const float* __restrict__ weights,
                     const float* __restrict__ ctrl_trans,
                     const float* __restrict__ ctrl_rots,
                     const float* __restrict__ ctrl_pos,
                     const int*   __restrict__ indices,
                     float* __restrict__ out_means,
                     float* __restrict__ out_quats,
                     int n)
{
    __shared__ uint4 sqb[K_TOT];                     // 4.8 KB
    __shared__ uint2 swj[NWARP][K_NB * KSTRIDE];     // 8 x 3.2 KB = 25.6 KB

    // ---- build fused control-point table once per (persistent) block ----
    for (int j = threadIdx.x; j < K_TOT; j += TPB) {
        float4 q = reinterpret_cast<const float4*>(ctrl_rots)[j];
        float dot = q.x * q.x + q.y * q.y + q.z * q.z + q.w * q.w;
        float inv = rsqrtf(fmaxf(dot, 1e-16f));
        float cw = q.x * inv, cx = q.y * inv, cy = q.z * inv, cz = q.w * inv;

        float px = ctrl_pos[j * 3 + 0];
        float py = ctrl_pos[j * 3 + 1];
        float pz = ctrl_pos[j * 3 + 2];

        float rpx, rpy, rpz;
        quat_rotate(cw, cx, cy, cz, px, py, pz, rpx, rpy, rpz);

        float b0 = px + ctrl_trans[j * 3 + 0] - rpx;
        float b1 = py + ctrl_trans[j * 3 + 1] - rpy;
        float b2 = pz + ctrl_trans[j * 3 + 2] - rpz;

        float delta = cw * cw - (cx * cx + cy * cy + cz * cz);

        uint4 e;
        e.x = pack_h2(cw, cx);
        e.y = pack_h2(cy, cz);
        e.z = pack_h2(b0, b1);
        e.w = pack_h2(b2, delta);
        sqb[j] = e;
    }
    __syncthreads();

    const int lane = threadIdx.x & 31;
    const int wid  = threadIdx.x >> 5;
    const int stride = gridDim.x * TPB;
    uint2* slice = swj[wid];

    for (int i0 = blockIdx.x * TPB + wid * 32; i0 < n; i0 += stride) {
        const int i = i0 + lane;

        __syncwarp();   // previous iteration's slice reads complete before overwrite

        // ---- stage this warp's 32 rows of (w, idx), transposed k-major ----
        // 32 gaussians x 10 floats = 320 floats = 80 float4s per array.
        if (i0 + 32 <= n) {
            const float4* wsrc = reinterpret_cast<const float4*>(weights + (size_t)i0 * K_NB);
            const int4*   isrc = reinterpret_cast<const int4*>(indices + (size_t)i0 * K_NB);

            #pragma unroll
            for (int r = 0; r < 3; r++) {
                const int u = lane + r * 32;
                if (r < 2 || u < 80) {             // r==2 only for lanes 0..15
                    float4 wa = wsrc[u];
                    int4   ia = isrc[u];
                    const int f = u * 4;
                    slice[((f + 0) % K_NB) * KSTRIDE + (f + 0) / K_NB] = make_uint2(__float_as_uint(wa.x), (unsigned)ia.x);
                    slice[((f + 1) % K_NB) * KSTRIDE + (f + 1) / K_NB] = make_uint2(__float_as_uint(wa.y), (unsigned)ia.y);
                    slice[((f + 2) % K_NB) * KSTRIDE + (f + 2) / K_NB] = make_uint2(__float_as_uint(wa.z), (unsigned)ia.z);
                    slice[((f + 3) % K_NB) * KSTRIDE + (f + 3) / K_NB] = make_uint2(__float_as_uint(wa.w), (unsigned)ia.w);
                }
            }
        } else {
            // partial warp at the very end: scalar guarded staging
            const int vf = (n - i0) * K_NB;
            for (int ff = lane; ff < vf; ff += 32) {
                float wv = weights[(size_t)i0 * K_NB + ff];
                int   jv = indices[(size_t)i0 * K_NB + ff];
                slice[(ff % K_NB) * KSTRIDE + ff / K_NB] = make_uint2(__float_as_uint(wv), (unsigned)jv);
            }
        }

        __syncwarp();   // staged data visible to all lanes

        if (i < n) {
            float mx = means[i * 3 + 0];
            float my = means[i * 3 + 1];
            float mz = means[i * 3 + 2];

            float P0 = 0.f, P1 = 0.f, P2 = 0.f;      // sum w (qv.m) qv
            float G0 = 0.f, G1 = 0.f, G2 = 0.f;      // sum w qw qv
            float B0 = 0.f, B1 = 0.f, B2 = 0.f;      // sum w b
            float L  = 0.f;                           // sum w delta
            float aq0 = 0.f, aq1 = 0.f, aq2 = 0.f, aq3 = 0.f;  // sum w q

            #pragma unroll
            for (int k = 0; k < K_NB; k++) {
                uint2 p = slice[k * KSTRIDE + lane];   // LDS.64 at the 2-wf floor
                const float w = __uint_as_float(p.x);
                const int   j = (int)p.y;

                uint4 e = sqb[j];
                float2 qwx = __half22float2(*reinterpret_cast<__half2*>(&e.x));
                float2 qyz = __half22float2(*reinterpret_cast<__half2*>(&e.y));
                float2 b01 = __half22float2(*reinterpret_cast<__half2*>(&e.z));
                float2 b2d = __half22float2(*reinterpret_cast<__half2*>(&e.w));

                const float qw = qwx.x, qx = qwx.y, qy = qyz.x, qz = qyz.y;

                float d  = fmaf(qz, mz, fmaf(qy, my, qx * mx));
                float wd = w * d;
                P0 = fmaf(wd, qx, P0);
                P1 = fmaf(wd, qy, P1);
                P2 = fmaf(wd, qz, P2);

                float wqw = w * qw;
                aq0 += wqw;
                G0 = fmaf(wqw, qx, G0);
                G1 = fmaf(wqw, qy, G1);
                G2 = fmaf(wqw, qz, G2);

                aq1 = fmaf(w, qx, aq1);
                aq2 = fmaf(w, qy, aq2);
                aq3 = fmaf(w, qz, aq3);

                L  = fmaf(w, b2d.y, L);
                B0 = fmaf(w, b01.x, B0);
                B1 = fmaf(w, b01.y, B1);
                B2 = fmaf(w, b2d.x, B2);
            }

            // ---- reconstruct blended mean: L*m + 2P + 2(G x m) + B ----
            float cx = G1 * mz - G2 * my;
            float cy = G2 * mx - G0 * mz;
            float cz = G0 * my - G1 * mx;

            float am0 = fmaf(L, mx, fmaf(2.f, P0 + cx, B0));
            float am1 = fmaf(L, my, fmaf(2.f, P1 + cy, B1));
            float am2 = fmaf(L, mz, fmaf(2.f, P2 + cz, B2));

            float4 gq = reinterpret_cast<const float4*>(quats)[i];   // (w,x,y,z)

            float dot = aq0 * aq0 + aq1 * aq1 + aq2 * aq2 + aq3 * aq3;
            float inv = rsqrtf(fmaxf(dot, 1e-16f));
            float aw = aq0 * inv, ax = aq1 * inv, ay = aq2 * inv, az = aq3 * inv;

            float bw = gq.x, bx = gq.y, by = gq.z, bz = gq.w;
            float4 qo;
            qo.x = aw * bw - ax * bx - ay * by - az * bz;
            qo.y = aw * bx + ax * bw + ay * bz - az * by;
            qo.z = aw * by - ax * bz + ay * bw + az * bx;
            qo.w = aw * bz + ax * by - ay * bx + az * bw;

            out_means[i * 3 + 0] = am0;
            out_means[i * 3 + 1] = am1;
            out_means[i * 3 + 2] = am2;
            reinterpret_cast<float4*>(out_quats)[i] = qo;
        }
    }
}

extern "C" void kernel_launch(void* const* d_in, const int* in_sizes, int n_in,
                              void* d_out, int out_size)
{
    const float* means      = (const float*)d_in[0];
    const float* quats      = (const float*)d_in[1];
    const float* weights    = (const float*)d_in[2];
    const float* ctrl_trans = (const float*)d_in[3];
    const float* ctrl_rots  = (const float*)d_in[4];
    const float* ctrl_pos   = (const float*)d_in[5];
    const int*   indices    = (const int*)d_in[6];

    int n = in_sizes[0] / 3;  // means is [N,3]

    float* out_means = (float*)d_out;
    float* out_quats = (float*)d_out + (size_t)n * 3;

    int max_blocks = NUM_SMS * BLKS_PER_SM;
    int need = (n + TPB - 1) / TPB;
    int blocks = need < max_blocks ? need : max_blocks;

    deform4d_kernel<<<blocks, TPB>>>(means, quats, weights,
                                     ctrl_trans, ctrl_rots, ctrl_pos,
                                     indices, out_means, out_quats, n);
}

// round 16
// speedup vs baseline: 1.3622x; 1.3622x over previous
#include <cuda_runtime.h>
#include <cuda_bf16.h>
#include <cuda_fp16.h>

#define K_NB    10
#define K_TOT   300
#define TPB     256
#define BLKS_PER_SM 6
#define NUM_SMS 148

// Fused fp16 table, 16B per control point (one LDS.128 per gather):
//  sqb[j] = { h2(qw,qx), h2(qy,qz), h2(b0,b1), h2(b2,delta) }
// q normalized in fp32; b = p + t - rot_q(p); delta = qw^2 - |qv|^2.
// Blend uses the linear decomposition:
//   sum_k w rot(m) + w b = L*m + 2P + 2(G x m) + B
//   L = sum w*delta, P = sum w*(qv.m)*qv, G = sum w*qw*qv, B = sum w*b

__device__ __forceinline__ void quat_rotate(float cw, float cx, float cy, float cz,
                                            float vx, float vy, float vz,
                                            float& ox, float& oy, float& oz)
{
    float tx = cy * vz - cz * vy;
    float ty = cz * vx - cx * vz;
    float tz = cx * vy - cy * vx;
    float ux = cy * tz - cz * ty;
    float uy = cz * tx - cx * tz;
    float uz = cx * ty - cy * tx;
    ox = fmaf(2.f, fmaf(cw, tx, ux), vx);
    oy = fmaf(2.f, fmaf(cw, ty, uy), vy);
    oz = fmaf(2.f, fmaf(cw, tz, uz), vz);
}

__device__ __forceinline__ unsigned int pack_h2(float a, float b)
{
    __half2 h = __floats2half2_rn(a, b);
    return *reinterpret_cast<unsigned int*>(&h);
}

__global__ __launch_bounds__(TPB, BLKS_PER_SM)
void deform4d_kernel(const float* __restrict__ means,
                     const float* __restrict__ quats,
                     const float* __restrict__ weights,
                     const float* __restrict__ ctrl_trans,
                     const float* __restrict__ ctrl_rots,
                     const float* __restrict__ ctrl_pos,
                     const int*   __restrict__ indices,
                     float* __restrict__ out_means,
                     float* __restrict__ out_quats,
                     int n)
{
    __shared__ uint4 sqb[K_TOT];   // 4.8 KB fused fp16 table

    // ---- build fused control-point table once per (persistent) block ----
    for (int j = threadIdx.x; j < K_TOT; j += TPB) {
        float4 q = reinterpret_cast<const float4*>(ctrl_rots)[j];
        float nrm = sqrtf(q.x * q.x + q.y * q.y + q.z * q.z + q.w * q.w);
        float inv = 1.0f / fmaxf(nrm, 1e-8f);
        float cw = q.x * inv, cx = q.y * inv, cy = q.z * inv, cz = q.w * inv;

        float px = ctrl_pos[j * 3 + 0];
        float py = ctrl_pos[j * 3 + 1];
        float pz = ctrl_pos[j * 3 + 2];

        float rpx, rpy, rpz;
        quat_rotate(cw, cx, cy, cz, px, py, pz, rpx, rpy, rpz);

        float b0 = px + ctrl_trans[j * 3 + 0] - rpx;
        float b1 = py + ctrl_trans[j * 3 + 1] - rpy;
        float b2 = pz + ctrl_trans[j * 3 + 2] - rpz;

        float delta = cw * cw - (cx * cx + cy * cy + cz * cz);

        uint4 e;
        e.x = pack_h2(cw, cx);
        e.y = pack_h2(cy, cz);
        e.z = pack_h2(b0, b1);
        e.w = pack_h2(b2, delta);
        sqb[j] = e;
    }
    __syncthreads();

    const int stride = gridDim.x * TPB;

    for (int i = blockIdx.x * TPB + threadIdx.x; i < n; i += stride) {
        float mx = means[i * 3 + 0];
        float my = means[i * 3 + 1];
        float mz = means[i * 3 + 2];

        const float2* wp = reinterpret_cast<const float2*>(weights + (size_t)i * K_NB);
        const int2*   ip = reinterpret_cast<const int2*>(indices + (size_t)i * K_NB);

        float P0 = 0.f, P1 = 0.f, P2 = 0.f;      // sum w (qv.m) qv
        float G0 = 0.f, G1 = 0.f, G2 = 0.f;      // sum w qw qv
        float B0 = 0.f, B1 = 0.f, B2 = 0.f;      // sum w b
        float L  = 0.f;                           // sum w delta
        float aq0 = 0.f, aq1 = 0.f, aq2 = 0.f, aq3 = 0.f;  // sum w q

        #pragma unroll
        for (int c = 0; c < K_NB / 2; c++) {
            float2 tw = wp[c];
            int2   ti = ip[c];

            #pragma unroll
            for (int h = 0; h < 2; h++) {
                const float w = (h == 0) ? tw.x : tw.y;
                const int   j = (h == 0) ? ti.x : ti.y;

                uint4 e = sqb[j];
                float2 qwx = __half22float2(*reinterpret_cast<__half2*>(&e.x));
                float2 qyz = __half22float2(*reinterpret_cast<__half2*>(&e.y));
                float2 b01 = __half22float2(*reinterpret_cast<__half2*>(&e.z));
                float2 b2d = __half22float2(*reinterpret_cast<__half2*>(&e.w));

                const float qw = qwx.x, qx = qwx.y, qy = qyz.x, qz = qyz.y;

                float d  = fmaf(qz, mz, fmaf(qy, my, qx * mx));
                float wd = w * d;
                P0 = fmaf(wd, qx, P0);
                P1 = fmaf(wd, qy, P1);
                P2 = fmaf(wd, qz, P2);

                float wqw = w * qw;
                aq0 += wqw;
                G0 = fmaf(wqw, qx, G0);
                G1 = fmaf(wqw, qy, G1);
                G2 = fmaf(wqw, qz, G2);

                aq1 = fmaf(w, qx, aq1);
                aq2 = fmaf(w, qy, aq2);
                aq3 = fmaf(w, qz, aq3);

                L  = fmaf(w, b2d.y, L);
                B0 = fmaf(w, b01.x, B0);
                B1 = fmaf(w, b01.y, B1);
                B2 = fmaf(w, b2d.x, B2);
            }
        }

        // ---- reconstruct blended mean: L*m + 2P + 2(G x m) + B ----
        float cx = G1 * mz - G2 * my;
        float cy = G2 * mx - G0 * mz;
        float cz = G0 * my - G1 * mx;

        float am0 = fmaf(L, mx, fmaf(2.f, P0 + cx, B0));
        float am1 = fmaf(L, my, fmaf(2.f, P1 + cy, B1));
        float am2 = fmaf(L, mz, fmaf(2.f, P2 + cz, B2));

        float4 gq = reinterpret_cast<const float4*>(quats)[i];   // (w,x,y,z)

        float nrm = sqrtf(aq0 * aq0 + aq1 * aq1 + aq2 * aq2 + aq3 * aq3);
        float inv = 1.0f / fmaxf(nrm, 1e-8f);
        float aw = aq0 * inv, ax = aq1 * inv, ay = aq2 * inv, az = aq3 * inv;

        float bw = gq.x, bx = gq.y, by = gq.z, bz = gq.w;
        float4 qo;
        qo.x = aw * bw - ax * bx - ay * by - az * bz;
        qo.y = aw * bx + ax * bw + ay * bz - az * by;
        qo.z = aw * by - ax * bz + ay * bw + az * bx;
        qo.w = aw * bz + ax * by - ay * bx + az * bw;

        out_means[i * 3 + 0] = am0;
        out_means[i * 3 + 1] = am1;
        out_means[i * 3 + 2] = am2;
        reinterpret_cast<float4*>(out_quats)[i] = qo;
    }
}

extern "C" void kernel_launch(void* const* d_in, const int* in_sizes, int n_in,
                              void* d_out, int out_size)
{
    const float* means      = (const float*)d_in[0];
    const float* quats      = (const float*)d_in[1];
    const float* weights    = (const float*)d_in[2];
    const float* ctrl_trans = (const float*)d_in[3];
    const float* ctrl_rots  = (const float*)d_in[4];
    const float* ctrl_pos   = (const float*)d_in[5];
    const int*   indices    = (const int*)d_in[6];

    int n = in_sizes[0] / 3;  // means is [N,3]

    float* out_means = (float*)d_out;
    float* out_quats = (float*)d_out + (size_t)n * 3;

    int max_blocks = NUM_SMS * BLKS_PER_SM;
    int need = (n + TPB - 1) / TPB;
    int blocks = need < max_blocks ? need : max_blocks;

    deform4d_kernel<<<blocks, TPB>>>(means, quats, weights,
                                     ctrl_trans, ctrl_rots, ctrl_pos,
                                     indices, out_means, out_quats, n);
}

// round 17
// speedup vs baseline: 1.4023x; 1.0294x over previous
#include <cuda_runtime.h>
#include <cuda_bf16.h>
#include <cuda_fp16.h>

#define K_NB    10
#define K_TOT   300
#define TPB     256
#define BLKS_PER_SM 6
#define NUM_SMS 148

// Fused fp16 table, 16B per control point (one LDS.128 per gather):
//  sqb[j] = { h2(qw,qx), h2(qy,qz), h2(b0,b1), h2(b2,delta) }
// q normalized in fp32; b = p + t - rot_q(p); delta = qw^2 - |qv|^2.
// Blend uses the linear decomposition:
//   sum_k w rot(m) + w b = L*m + 2P + 2(G x m) + B
// Final quat: normalize(blend) (x) gq  ==  (blend (x) gq) * rsqrt(|blend|^2)

__device__ __forceinline__ void quat_rotate(float cw, float cx, float cy, float cz,
                                            float vx, float vy, float vz,
                                            float& ox, float& oy, float& oz)
{
    float tx = cy * vz - cz * vy;
    float ty = cz * vx - cx * vz;
    float tz = cx * vy - cy * vx;
    float ux = cy * tz - cz * ty;
    float uy = cz * tx - cx * tz;
    float uz = cx * ty - cy * tx;
    ox = fmaf(2.f, fmaf(cw, tx, ux), vx);
    oy = fmaf(2.f, fmaf(cw, ty, uy), vy);
    oz = fmaf(2.f, fmaf(cw, tz, uz), vz);
}

__device__ __forceinline__ unsigned int pack_h2(float a, float b)
{
    __half2 h = __floats2half2_rn(a, b);
    return *reinterpret_cast<unsigned int*>(&h);
}

__global__ __launch_bounds__(TPB, BLKS_PER_SM)
void deform4d_kernel(const float* __restrict__ means,
                     const float* __restrict__ quats,
                     const float* __restrict__ weights,
                     const float* __restrict__ ctrl_trans,
                     const float* __restrict__ ctrl_rots,
                     const float* __restrict__ ctrl_pos,
                     const int*   __restrict__ indices,
                     float* __restrict__ out_means,
                     float* __restrict__ out_quats,
                     int n)
{
    __shared__ uint4 sqb[K_TOT];   // 4.8 KB fused fp16 table

    // ---- build fused control-point table once per (persistent) block ----
    for (int j = threadIdx.x; j < K_TOT; j += TPB) {
        float4 q = reinterpret_cast<const float4*>(ctrl_rots)[j];
        float dot = q.x * q.x + q.y * q.y + q.z * q.z + q.w * q.w;
        float inv = rsqrtf(fmaxf(dot, 1e-16f));
        float cw = q.x * inv, cx = q.y * inv, cy = q.z * inv, cz = q.w * inv;

        float px = ctrl_pos[j * 3 + 0];
        float py = ctrl_pos[j * 3 + 1];
        float pz = ctrl_pos[j * 3 + 2];

        float rpx, rpy, rpz;
        quat_rotate(cw, cx, cy, cz, px, py, pz, rpx, rpy, rpz);

        float b0 = px + ctrl_trans[j * 3 + 0] - rpx;
        float b1 = py + ctrl_trans[j * 3 + 1] - rpy;
        float b2 = pz + ctrl_trans[j * 3 + 2] - rpz;

        float delta = cw * cw - (cx * cx + cy * cy + cz * cz);

        uint4 e;
        e.x = pack_h2(cw, cx);
        e.y = pack_h2(cy, cz);
        e.z = pack_h2(b0, b1);
        e.w = pack_h2(b2, delta);
        sqb[j] = e;
    }
    __syncthreads();

    const int stride = gridDim.x * TPB;

    for (int i = blockIdx.x * TPB + threadIdx.x; i < n; i += stride) {
        float mx = means[i * 3 + 0];
        float my = means[i * 3 + 1];
        float mz = means[i * 3 + 2];

        const float2* wp = reinterpret_cast<const float2*>(weights + (size_t)i * K_NB);
        const int2*   ip = reinterpret_cast<const int2*>(indices + (size_t)i * K_NB);

        float P0 = 0.f, P1 = 0.f, P2 = 0.f;      // sum w (qv.m) qv
        float G0 = 0.f, G1 = 0.f, G2 = 0.f;      // sum w qw qv
        float B0 = 0.f, B1 = 0.f, B2 = 0.f;      // sum w b
        float L  = 0.f;                           // sum w delta
        float aq0 = 0.f, aq1 = 0.f, aq2 = 0.f, aq3 = 0.f;  // sum w q

        #pragma unroll
        for (int c = 0; c < K_NB / 2; c++) {
            float2 tw = wp[c];
            int2   ti = ip[c];

            #pragma unroll
            for (int h = 0; h < 2; h++) {
                const float w = (h == 0) ? tw.x : tw.y;
                const int   j = (h == 0) ? ti.x : ti.y;

                uint4 e = sqb[j];
                float2 qwx = __half22float2(*reinterpret_cast<__half2*>(&e.x));
                float2 qyz = __half22float2(*reinterpret_cast<__half2*>(&e.y));
                float2 b01 = __half22float2(*reinterpret_cast<__half2*>(&e.z));
                float2 b2d = __half22float2(*reinterpret_cast<__half2*>(&e.w));

                const float qw = qwx.x, qx = qwx.y, qy = qyz.x, qz = qyz.y;

                float d  = fmaf(qz, mz, fmaf(qy, my, qx * mx));
                float wd = w * d;
                P0 = fmaf(wd, qx, P0);
                P1 = fmaf(wd, qy, P1);
                P2 = fmaf(wd, qz, P2);

                float wqw = w * qw;
                aq0 += wqw;
                G0 = fmaf(wqw, qx, G0);
                G1 = fmaf(wqw, qy, G1);
                G2 = fmaf(wqw, qz, G2);

                aq1 = fmaf(w, qx, aq1);
                aq2 = fmaf(w, qy, aq2);
                aq3 = fmaf(w, qz, aq3);

                L  = fmaf(w, b2d.y, L);
                B0 = fmaf(w, b01.x, B0);
                B1 = fmaf(w, b01.y, B1);
                B2 = fmaf(w, b2d.x, B2);
            }
        }

        // ---- reconstruct blended mean: L*m + 2P + 2(G x m) + B ----
        float cx = G1 * mz - G2 * my;
        float cy = G2 * mx - G0 * mz;
        float cz = G0 * my - G1 * mx;

        float am0 = fmaf(L, mx, fmaf(2.f, P0 + cx, B0));
        float am1 = fmaf(L, my, fmaf(2.f, P1 + cy, B1));
        float am2 = fmaf(L, mz, fmaf(2.f, P2 + cz, B2));

        float4 gq = reinterpret_cast<const float4*>(quats)[i];   // (w,x,y,z)

        // Hamilton product FIRST (independent of normalization), scale after:
        // normalize(aq) (x) gq == (aq (x) gq) * rsqrt(|aq|^2)
        float bw = gq.x, bx = gq.y, by = gq.z, bz = gq.w;
        float h0 = aq0 * bw - aq1 * bx - aq2 * by - aq3 * bz;
        float h1 = aq0 * bx + aq1 * bw + aq2 * bz - aq3 * by;
        float h2 = aq0 * by - aq1 * bz + aq2 * bw + aq3 * bx;
        float h3 = aq0 * bz + aq1 * by - aq2 * bx + aq3 * bw;

        float dot = aq0 * aq0 + aq1 * aq1 + aq2 * aq2 + aq3 * aq3;
        float inv = rsqrtf(fmaxf(dot, 1e-16f));

        float4 qo;
        qo.x = h0 * inv;
        qo.y = h1 * inv;
        qo.z = h2 * inv;
        qo.w = h3 * inv;

        out_means[i * 3 + 0] = am0;
        out_means[i * 3 + 1] = am1;
        out_means[i * 3 + 2] = am2;
        reinterpret_cast<float4*>(out_quats)[i] = qo;
    }
}

extern "C" void kernel_launch(void* const* d_in, const int* in_sizes, int n_in,
                              void* d_out, int out_size)
{
    const float* means      = (const float*)d_in[0];
    const float* quats      = (const float*)d_in[1];
    const float* weights    = (const float*)d_in[2];
    const float* ctrl_trans = (const float*)d_in[3];
    const float* ctrl_rots  = (const float*)d_in[4];
    const float* ctrl_pos   = (const float*)d_in[5];
    const int*   indices    = (const int*)d_in[6];

    int n = in_sizes[0] / 3;  // means is [N,3]

    float* out_means = (float*)d_out;
    float* out_quats = (float*)d_out + (size_t)n * 3;

    int max_blocks = NUM_SMS * BLKS_PER_SM;
    int need = (n + TPB - 1) / TPB;
    int blocks = need < max_blocks ? need : max_blocks;

    deform4d_kernel<<<blocks, TPB>>>(means, quats, weights,
                                     ctrl_trans, ctrl_rots, ctrl_pos,
                                     indices, out_means, out_quats, n);
}